// round 8
// baseline (speedup 1.0000x reference)
#include <cuda_runtime.h>
#include <cuda_fp16.h>
#include <cstddef>

// ForwardSim, fully tensorized HMMA (sm_103 baseline mma.sync, 3-term fp16).
// R8 = R7 + (a) interleaved mma issue across independent accumulator chains
// (GEMM2 nf-pairs, GEMM1 nfo-pairs) to hide HMMA RAW latency that volatile-asm
// ordering otherwise exposes, and (b) idm/merg prefetch for t+1 issued at the
// top of the mma phase so the serial env phase never waits on gmem.

using u32 = unsigned int;
using u64 = unsigned long long;

namespace {
constexpr int kB = 32768, kT = 50, kH = 128, kM = 64, kThreads = 256;

constexpr int OFF_BFRAG = 0;        // 65536: W2 frags [ch][kb][nf][lane] 16B
constexpr int OFF_PACC  = 65536;    // 32768: projAcc frags [m16][nf1][lane] 16B
constexpr int OFF_W1EB  = 98304;    // 8192:  W1e B-frags [nf1][lane] 16B
constexpr int OFF_ENV   = 106496;   // 3328:  64 x 13 f32
constexpr int OFF_BW    = 109824;   // 1024:  (b2 pair, W3 pair) per col pair
constexpr int OFF_PART  = 110848;   // 512:   2 x 64 partials
constexpr int OFF_SC    = 111360;   // 64
constexpr int SMEM_BYTES = 111424;
constexpr int OFF_W1P   = 0;        // phase alias in BFRAG: W1[0:64] natural
} // namespace

__device__ __forceinline__ u64 pack_dup(float v) {
    u64 r; asm("mov.b64 %0, {%1, %1};" : "=l"(r) : "f"(v)); return r;
}
__device__ __forceinline__ u64 pack2(float a, float b) {
    u64 r; asm("mov.b64 %0, {%1, %2};" : "=l"(r) : "f"(a), "f"(b)); return r;
}
__device__ __forceinline__ void unpack2(u64 v, float& a, float& b) {
    asm("mov.b64 {%0, %1}, %2;" : "=f"(a), "=f"(b) : "l"(v));
}
__device__ __forceinline__ u64 fma2(u64 a, u64 b, u64 c) {
    u64 d; asm("fma.rn.f32x2 %0, %1, %2, %3;" : "=l"(d) : "l"(a), "l"(b), "l"(c));
    return d;
}
__device__ __forceinline__ void split2(float f0, float f1, u32& hi, u32& lo) {
    __half h0 = __float2half_rn(f0), h1 = __float2half_rn(f1);
    __half2 hh = __halves2half2(h0, h1);
    hi = reinterpret_cast<u32&>(hh);
    __half2 ll = __floats2half2_rn(f0 - __half2float(h0),
                                   f1 - __half2float(h1));
    lo = reinterpret_cast<u32&>(ll);
}
__device__ __forceinline__ void mma16816(float d[4], u32 a0, u32 a1, u32 a2,
                                         u32 a3, u32 b0, u32 b1) {
    asm volatile(
        "mma.sync.aligned.m16n8k16.row.col.f32.f16.f16.f32 "
        "{%0,%1,%2,%3}, {%4,%5,%6,%7}, {%8,%9}, {%0,%1,%2,%3};"
        : "+f"(d[0]), "+f"(d[1]), "+f"(d[2]), "+f"(d[3])
        : "r"(a0), "r"(a1), "r"(a2), "r"(a3), "r"(b0), "r"(b1));
}

__global__ void __launch_bounds__(kThreads, 2)
fsim_mma(const float* __restrict__ proj, const float* __restrict__ idm,
         const float* __restrict__ merg, const float* __restrict__ W1,
         const float* __restrict__ b1,   const float* __restrict__ W2,
         const float* __restrict__ b2,   const float* __restrict__ W3,
         const float* __restrict__ b3,   const float* __restrict__ smean,
         const float* __restrict__ svar, float* __restrict__ out)
{
    extern __shared__ char smem[];
    float* smf = (float*)smem;

    const int tid = threadIdx.x, wid = tid >> 5, lane = tid & 31;
    const int mbW = wid >> 1, ch = wid & 1, g = lane >> 2, q = lane & 3;
    const int rowBase = blockIdx.x * kM;

    // ---------------- phase A: stage W1[0:64] natural + tables -------------
    for (int i = tid; i < 64 * kH; i += kThreads)
        smf[(OFF_W1P >> 2) + i] = W1[i];
    if (tid < 64) {
        int c = tid * 2;
        float4 v;
        v.x = b2[c]; v.y = b2[c + 1]; v.z = W3[c]; v.w = W3[c + 1];
        *(float4*)(smem + OFF_BW + tid * 16) = v;
    }
    if (tid < 6) {
        smf[(OFF_SC >> 2) + tid]     = smean[tid];
        smf[(OFF_SC >> 2) + 8 + tid] = rsqrtf(svar[tid]);
    }
    __syncthreads();

    // -------- phase B: projAcc = proj@W1[:64]+b1 -> fragment-native fp32 ---
    for (int task = tid; task < 512; task += kThreads) {
        int r = task >> 3, cg = task & 7;   // row (0..63), 16-col group
        const float* prow = proj + (size_t)(rowBase + r) * 64;
        u64 acc[8];
        #pragma unroll
        for (int e = 0; e < 8; e++)
            acc[e] = pack2(__ldg(&b1[cg * 16 + 2 * e]),
                           __ldg(&b1[cg * 16 + 2 * e + 1]));
        #pragma unroll 4
        for (int k4 = 0; k4 < 16; k4++) {
            float4 av = __ldg((const float4*)(prow + k4 * 4));
            float avv[4] = {av.x, av.y, av.z, av.w};
            #pragma unroll
            for (int e2 = 0; e2 < 4; e2++) {
                u64 a = pack_dup(avv[e2]);
                const u64* w = (const u64*)
                    &smf[(OFF_W1P >> 2) + (k4 * 4 + e2) * 128 + cg * 16];
                #pragma unroll
                for (int e = 0; e < 8; e++) acc[e] = fma2(a, w[e], acc[e]);
            }
        }
        int m16 = r >> 4, half = (r >> 3) & 1, lrow = r & 7;
        #pragma unroll
        for (int e = 0; e < 8; e++) {
            int nf1 = cg * 2 + (e >> 2);
            int ln  = lrow * 4 + (e & 3);
            float lo_, hi_;
            unpack2(acc[e], lo_, hi_);
            *(float2*)(smem + OFF_PACC +
                       (size_t)(((m16 * 16 + nf1) * 32 + ln) * 16) + half * 8)
                = make_float2(lo_, hi_);
        }
    }
    __syncthreads();

    // -------- phase C: W2 -> fragment fp16 hi/lo (overwrites W1P) ----------
    for (int i = tid; i < 4096; i += kThreads) {
        int t  = i & 31, nf = (i >> 5) & 7, kb = (i >> 8) & 7, c2 = (i >> 11) & 1;
        int gg = t >> 2, qq = t & 3;
        int n  = c2 * 64 + nf * 8 + gg;
        int k0 = kb * 16 + qq * 2;
        float w00 = W2[(size_t)k0 * 128 + n];
        float w01 = W2[(size_t)(k0 + 1) * 128 + n];
        float w10 = W2[(size_t)(k0 + 8) * 128 + n];
        float w11 = W2[(size_t)(k0 + 9) * 128 + n];
        u32 h0, l0, h1v, l1v;
        split2(w00, w01, h0, l0);
        split2(w10, w11, h1v, l1v);
        ulonglong2 e;
        e.x = ((u64)h1v << 32) | h0;
        e.y = ((u64)l1v << 32) | l0;
        *(ulonglong2*)(smem + OFF_BFRAG +
                       (size_t)(((c2 * 8 + kb) * 8 + nf) * 32 + t) * 16) = e;
    }
    // -------- phase C2: W1e (W1 rows 64..72) -> B-frags, K=16 padded -------
    for (int i = tid; i < 512; i += kThreads) {
        int t = i & 31, nf = i >> 5;        // nf 0..15
        int gg = t >> 2, qq = t & 3;
        int n  = nf * 8 + gg;
        int k0 = qq * 2;
        float w00 = W1[(size_t)(64 + k0) * 128 + n];
        float w01 = W1[(size_t)(64 + k0 + 1) * 128 + n];
        float w10 = (qq == 0) ? W1[(size_t)72 * 128 + n] : 0.f;  // k=8 only
        u32 h0, l0, h1v, l1v;
        split2(w00, w01, h0, l0);
        split2(w10, 0.f, h1v, l1v);
        ulonglong2 e;
        e.x = ((u64)h1v << 32) | h0;
        e.y = ((u64)l1v << 32) | l0;
        *(ulonglong2*)(smem + OFF_W1EB + (size_t)(nf * 32 + t) * 16) = e;
    }
    __syncthreads();

    const float b3v = __ldg(&b3[0]);
    float ego_v = 0.f, ego_x = 0.f, act_c = 0.f;   // carry in tid<64

    // ---- prefetch idm/merg for t=0 ----
    float4 pf_a0 = make_float4(0.f, 0.f, 0.f, 0.f);
    float pf_s4 = 0.f, pf_s5 = 0.f, pf_s11 = 0.f;
    float pf_m0 = 0.f, pf_m1 = 0.f, pf_m2 = 0.f;
    if (tid < kM) {
        const float* sp = idm + (size_t)(rowBase + tid) * (kT * 12);
        pf_a0 = __ldg((const float4*)sp);
        float2 s45 = __ldg((const float2*)(sp + 4));
        pf_s4 = s45.x; pf_s5 = s45.y;
        pf_s11 = __ldg(sp + 11);
        const float* mp = merg + (size_t)(rowBase + tid) * (kT * 3);
        pf_m0 = __ldg(mp); pf_m1 = __ldg(mp + 1); pf_m2 = __ldg(mp + 2);
    }

    // ================= timestep loop =================
    for (int t = 0; t < kT; t++) {
        // ---- env features (one thread per row) from prefetched inputs ----
        if (tid < kM) {
            if (t == 0) { ego_v = pf_a0.x; ego_x = pf_a0.w; }
            else {
                ego_v = fmaf(act_c, 0.1f, ego_v);
                ego_x = ego_x + ego_v * 0.1f + act_c * 0.005f;
            }
            float ev[6];
            ev[0] = ego_v;
            ev[1] = pf_a0.y;
            ev[2] = ego_v - pf_a0.y;
            ev[3] = pf_s4 - ego_x;
            ev[4] = (ego_v - pf_a0.z) * pf_s11;
            ev[5] = (pf_s5 - ego_x) * pf_s11 + (1.0f - pf_s11) * 100.0f;
            #pragma unroll
            for (int j = 0; j < 6; j++)
                smf[(OFF_ENV >> 2) + tid * 13 + j] =
                    (ev[j] - smf[(OFF_SC >> 2) + j]) * smf[(OFF_SC >> 2) + 8 + j];
            smf[(OFF_ENV >> 2) + tid * 13 + 6] = pf_m0;
            smf[(OFF_ENV >> 2) + tid * 13 + 7] = pf_m1;
            smf[(OFF_ENV >> 2) + tid * 13 + 8] = pf_m2;
        }
        __syncthreads();

        // ---- prefetch t+1 (latency hidden under the mma phase) ----
        if (tid < kM && t + 1 < kT) {
            const float* sp = idm + (size_t)(rowBase + tid) * (kT * 12) +
                              (t + 1) * 12;
            pf_a0 = __ldg((const float4*)sp);
            float2 s45 = __ldg((const float2*)(sp + 4));
            pf_s4 = s45.x; pf_s5 = s45.y;
            pf_s11 = __ldg(sp + 11);
            const float* mp = merg + (size_t)(rowBase + tid) * (kT * 3) +
                              (t + 1) * 3;
            pf_m0 = __ldg(mp); pf_m1 = __ldg(mp + 1); pf_m2 = __ldg(mp + 2);
        }

        // ---- env A-fragments for this warp's 2 row-slots (g, g+8) ----
        u32 ehi[2], elo[2], fhi[2], flo[2];
        #pragma unroll
        for (int p = 0; p < 2; p++) {
            int rr = mbW * 16 + p * 8 + g;
            const float* ep = &smf[(OFF_ENV >> 2) + rr * 13];
            float e0 = ep[2 * q], e1 = ep[2 * q + 1];
            float e8 = (q == 0) ? ep[8] : 0.f;
            split2(e0, e1, ehi[p], elo[p]);
            split2(e8, 0.f, fhi[p], flo[p]);
        }

        float d[8][4];
        #pragma unroll
        for (int nf = 0; nf < 8; nf++)
            d[nf][0] = d[nf][1] = d[nf][2] = d[nf][3] = 0.f;

        // GEMM1 for a k-block: both nfo chains interleaved
        auto gemm1_mma = [&](int kb, float dd[2][4]) {
            int nf1 = kb * 2;
            float4 pv0 = *(const float4*)(smem + OFF_PACC +
                (size_t)(((mbW * 16 + nf1) * 32 + lane) * 16));
            float4 pv1 = *(const float4*)(smem + OFF_PACC +
                (size_t)(((mbW * 16 + nf1 + 1) * 32 + lane) * 16));
            ulonglong2 bfA = *(const ulonglong2*)(smem + OFF_W1EB +
                (size_t)((nf1 * 32 + lane) * 16));
            ulonglong2 bfB = *(const ulonglong2*)(smem + OFF_W1EB +
                (size_t)(((nf1 + 1) * 32 + lane) * 16));
            dd[0][0] = pv0.x; dd[0][1] = pv0.y; dd[0][2] = pv0.z; dd[0][3] = pv0.w;
            dd[1][0] = pv1.x; dd[1][1] = pv1.y; dd[1][2] = pv1.z; dd[1][3] = pv1.w;
            u32 hA0 = (u32)bfA.x, hA1 = (u32)(bfA.x >> 32);
            u32 lA0 = (u32)bfA.y, lA1 = (u32)(bfA.y >> 32);
            u32 hB0 = (u32)bfB.x, hB1 = (u32)(bfB.x >> 32);
            u32 lB0 = (u32)bfB.y, lB1 = (u32)(bfB.y >> 32);
            mma16816(dd[0], ehi[0], ehi[1], fhi[0], fhi[1], hA0, hA1);
            mma16816(dd[1], ehi[0], ehi[1], fhi[0], fhi[1], hB0, hB1);
            mma16816(dd[0], elo[0], elo[1], flo[0], flo[1], hA0, hA1);
            mma16816(dd[1], elo[0], elo[1], flo[0], flo[1], hB0, hB1);
            mma16816(dd[0], ehi[0], ehi[1], fhi[0], fhi[1], lA0, lA1);
            mma16816(dd[1], ehi[0], ehi[1], fhi[0], fhi[1], lB0, lB1);
        };
        auto gemm1_split = [&](const float dd[2][4], u32 Ah[4], u32 Al[4]) {
            #pragma unroll
            for (int nfo = 0; nfo < 2; nfo++) {
                u32 h01, l01, h23, l23;
                split2(fmaxf(dd[nfo][0], 0.f), fmaxf(dd[nfo][1], 0.f), h01, l01);
                split2(fmaxf(dd[nfo][2], 0.f), fmaxf(dd[nfo][3], 0.f), h23, l23);
                Ah[nfo * 2 + 0] = h01;  Al[nfo * 2 + 0] = l01;
                Ah[nfo * 2 + 1] = h23;  Al[nfo * 2 + 1] = l23;
            }
        };

        u32 Ah[2][4], Al[2][4];
        float dd[2][4];
        gemm1_mma(0, dd);
        gemm1_split(dd, Ah[0], Al[0]);

        #pragma unroll
        for (int kb = 0; kb < 8; kb++) {
            const int cur = kb & 1, nxt = cur ^ 1;
            float ddn[2][4];
            if (kb < 7) gemm1_mma(kb + 1, ddn);   // overlap with GEMM2 below
            const char* bfp = smem + OFF_BFRAG +
                              (size_t)((ch * 8 + kb) * 8) * 512 + lane * 16;
            #pragma unroll
            for (int nf2 = 0; nf2 < 4; nf2++) {   // nf pairs, interleaved issue
                const int nA = nf2 * 2, nB = nA + 1;
                ulonglong2 bfA = *(const ulonglong2*)(bfp + nA * 512);
                ulonglong2 bfB = *(const ulonglong2*)(bfp + nB * 512);
                u32 hA0 = (u32)bfA.x, hA1 = (u32)(bfA.x >> 32);
                u32 lA0 = (u32)bfA.y, lA1 = (u32)(bfA.y >> 32);
                u32 hB0 = (u32)bfB.x, hB1 = (u32)(bfB.x >> 32);
                u32 lB0 = (u32)bfB.y, lB1 = (u32)(bfB.y >> 32);
                mma16816(d[nA], Ah[cur][0], Ah[cur][1], Ah[cur][2], Ah[cur][3],
                         hA0, hA1);
                mma16816(d[nB], Ah[cur][0], Ah[cur][1], Ah[cur][2], Ah[cur][3],
                         hB0, hB1);
                mma16816(d[nA], Al[cur][0], Al[cur][1], Al[cur][2], Al[cur][3],
                         hA0, hA1);
                mma16816(d[nB], Al[cur][0], Al[cur][1], Al[cur][2], Al[cur][3],
                         hB0, hB1);
                mma16816(d[nA], Ah[cur][0], Ah[cur][1], Ah[cur][2], Ah[cur][3],
                         lA0, lA1);
                mma16816(d[nB], Ah[cur][0], Ah[cur][1], Ah[cur][2], Ah[cur][3],
                         lB0, lB1);
            }
            if (kb < 7) gemm1_split(ddn, Ah[nxt], Al[nxt]);
        }

        // ---- epilogue: relu(D + b2) . W3 ----
        float s0 = 0.f, s1 = 0.f;
        #pragma unroll
        for (int nf = 0; nf < 8; nf++) {
            float4 bw = *(const float4*)(smem + OFF_BW +
                                         (ch * 32 + nf * 4 + q) * 16);
            s0 += fmaxf(d[nf][0] + bw.x, 0.f) * bw.z +
                  fmaxf(d[nf][1] + bw.y, 0.f) * bw.w;
            s1 += fmaxf(d[nf][2] + bw.x, 0.f) * bw.z +
                  fmaxf(d[nf][3] + bw.y, 0.f) * bw.w;
        }
        s0 += __shfl_xor_sync(0xFFFFFFFFu, s0, 1);
        s0 += __shfl_xor_sync(0xFFFFFFFFu, s0, 2);
        s1 += __shfl_xor_sync(0xFFFFFFFFu, s1, 1);
        s1 += __shfl_xor_sync(0xFFFFFFFFu, s1, 2);
        if (q == 0) {
            smf[(OFF_PART >> 2) + ch * 64 + mbW * 16 + g]     = s0;
            smf[(OFF_PART >> 2) + ch * 64 + mbW * 16 + g + 8] = s1;
        }
        __syncthreads();

        if (tid < kM) {
            float a = smf[(OFF_PART >> 2) + tid] +
                      smf[(OFF_PART >> 2) + 64 + tid] + b3v;
            act_c = a;
            out[(size_t)(rowBase + tid) * kT + t] = a;
        }
        // env(t+1) is written by the same tid<64 threads; every other warp
        // re-blocks at the next __syncthreads() before reading env.
    }
}

extern "C" void kernel_launch(void* const* d_in, const int* in_sizes, int n_in,
                              void* d_out, int out_size)
{
    (void)in_sizes; (void)n_in; (void)out_size;
    const float* proj  = (const float*)d_in[0];
    const float* idm   = (const float*)d_in[1];
    const float* merg  = (const float*)d_in[2];
    const float* W1    = (const float*)d_in[3];
    const float* b1    = (const float*)d_in[4];
    const float* W2    = (const float*)d_in[5];
    const float* b2    = (const float*)d_in[6];
    const float* W3    = (const float*)d_in[7];
    const float* b3    = (const float*)d_in[8];
    const float* smean = (const float*)d_in[9];
    const float* svar  = (const float*)d_in[10];
    float* out = (float*)d_out;

    cudaFuncSetAttribute(fsim_mma, cudaFuncAttributeMaxDynamicSharedMemorySize,
                         SMEM_BYTES);
    fsim_mma<<<kB / kM, kThreads, SMEM_BYTES>>>(
        proj, idm, merg, W1, b1, W2, b2, W3, b3, smean, svar, out);
}

// round 9
// speedup vs baseline: 1.0922x; 1.0922x over previous
#include <cuda_runtime.h>
#include <cuda_fp16.h>
#include <cstddef>

// ForwardSim, fully tensorized HMMA (sm_103 baseline mma.sync, 3-term fp16).
// R9 = R8 + (a) per-pair named barriers: each 64-thread warp-pair (16 rows x
// 128 cols) runs its own 50-step pipeline (env rows / partials / carry are
// pair-private; weights read-only), removing whole-CTA lockstep bubbles;
// (b) GEMM1 via m16n8k8 (env features 0-7) + exact fp32 rank-1 FMA for
// feature 8, cutting GEMM1 tensor cost in half.

using u32 = unsigned int;
using u64 = unsigned long long;

namespace {
constexpr int kB = 32768, kT = 50, kH = 128, kM = 64, kThreads = 256;

constexpr int OFF_BFRAG = 0;        // 65536: W2 frags [ch][kb][nf][lane] 16B
constexpr int OFF_PACC  = 65536;    // 32768: projAcc frags [m16][nf1][lane] 16B
constexpr int OFF_W1EB  = 98304;    // 4096:  W1e k8 B-frags [nf1][lane] 8B
constexpr int OFF_W72   = 102400;   // 512:   W1 row 72 natural
constexpr int OFF_ENV   = 102912;   // 3328:  64 x 13 f32 (pair-private rows)
constexpr int OFF_BW    = 106240;   // 1024:  (b2 pair, W3 pair) per col pair
constexpr int OFF_PART  = 107264;   // 512:   [mb][ch][row16] partials
constexpr int OFF_SC    = 107776;   // 64
constexpr int SMEM_BYTES = 107840;
constexpr int OFF_W1P   = 0;        // phase alias in BFRAG: W1[0:64] natural
} // namespace

__device__ __forceinline__ u64 pack_dup(float v) {
    u64 r; asm("mov.b64 %0, {%1, %1};" : "=l"(r) : "f"(v)); return r;
}
__device__ __forceinline__ u64 pack2(float a, float b) {
    u64 r; asm("mov.b64 %0, {%1, %2};" : "=l"(r) : "f"(a), "f"(b)); return r;
}
__device__ __forceinline__ void unpack2(u64 v, float& a, float& b) {
    asm("mov.b64 {%0, %1}, %2;" : "=f"(a), "=f"(b) : "l"(v));
}
__device__ __forceinline__ u64 fma2(u64 a, u64 b, u64 c) {
    u64 d; asm("fma.rn.f32x2 %0, %1, %2, %3;" : "=l"(d) : "l"(a), "l"(b), "l"(c));
    return d;
}
__device__ __forceinline__ void split2(float f0, float f1, u32& hi, u32& lo) {
    __half h0 = __float2half_rn(f0), h1 = __float2half_rn(f1);
    __half2 hh = __halves2half2(h0, h1);
    hi = reinterpret_cast<u32&>(hh);
    __half2 ll = __floats2half2_rn(f0 - __half2float(h0),
                                   f1 - __half2float(h1));
    lo = reinterpret_cast<u32&>(ll);
}
__device__ __forceinline__ void mma16816(float d[4], u32 a0, u32 a1, u32 a2,
                                         u32 a3, u32 b0, u32 b1) {
    asm volatile(
        "mma.sync.aligned.m16n8k16.row.col.f32.f16.f16.f32 "
        "{%0,%1,%2,%3}, {%4,%5,%6,%7}, {%8,%9}, {%0,%1,%2,%3};"
        : "+f"(d[0]), "+f"(d[1]), "+f"(d[2]), "+f"(d[3])
        : "r"(a0), "r"(a1), "r"(a2), "r"(a3), "r"(b0), "r"(b1));
}
__device__ __forceinline__ void mma1688(float d[4], u32 a0, u32 a1, u32 b0) {
    asm volatile(
        "mma.sync.aligned.m16n8k8.row.col.f32.f16.f16.f32 "
        "{%0,%1,%2,%3}, {%4,%5}, {%6}, {%0,%1,%2,%3};"
        : "+f"(d[0]), "+f"(d[1]), "+f"(d[2]), "+f"(d[3])
        : "r"(a0), "r"(a1), "r"(b0));
}
#define BAR_PAIR(id) asm volatile("bar.sync %0, 64;" :: "r"(id) : "memory")

__global__ void __launch_bounds__(kThreads, 2)
fsim_mma(const float* __restrict__ proj, const float* __restrict__ idm,
         const float* __restrict__ merg, const float* __restrict__ W1,
         const float* __restrict__ b1,   const float* __restrict__ W2,
         const float* __restrict__ b2,   const float* __restrict__ W3,
         const float* __restrict__ b3,   const float* __restrict__ smean,
         const float* __restrict__ svar, float* __restrict__ out)
{
    extern __shared__ char smem[];
    float* smf = (float*)smem;

    const int tid = threadIdx.x, wid = tid >> 5, lane = tid & 31;
    const int mbW = wid >> 1, ch = wid & 1, g = lane >> 2, q = lane & 3;
    const int rowBase = blockIdx.x * kM;
    const int barId = mbW + 1;

    // ---------------- phase A: stage W1[0:64] natural + tables -------------
    for (int i = tid; i < 64 * kH; i += kThreads)
        smf[(OFF_W1P >> 2) + i] = W1[i];
    if (tid < 64) {
        int c = tid * 2;
        float4 v;
        v.x = b2[c]; v.y = b2[c + 1]; v.z = W3[c]; v.w = W3[c + 1];
        *(float4*)(smem + OFF_BW + tid * 16) = v;
    }
    if (tid < 6) {
        smf[(OFF_SC >> 2) + tid]     = smean[tid];
        smf[(OFF_SC >> 2) + 8 + tid] = rsqrtf(svar[tid]);
    }
    if (tid < 128)
        smf[(OFF_W72 >> 2) + tid] = W1[(size_t)72 * 128 + tid];
    __syncthreads();

    // -------- phase B: projAcc = proj@W1[:64]+b1 -> fragment-native fp32 ---
    for (int task = tid; task < 512; task += kThreads) {
        int r = task >> 3, cg = task & 7;   // row (0..63), 16-col group
        const float* prow = proj + (size_t)(rowBase + r) * 64;
        u64 acc[8];
        #pragma unroll
        for (int e = 0; e < 8; e++)
            acc[e] = pack2(__ldg(&b1[cg * 16 + 2 * e]),
                           __ldg(&b1[cg * 16 + 2 * e + 1]));
        #pragma unroll 4
        for (int k4 = 0; k4 < 16; k4++) {
            float4 av = __ldg((const float4*)(prow + k4 * 4));
            float avv[4] = {av.x, av.y, av.z, av.w};
            #pragma unroll
            for (int e2 = 0; e2 < 4; e2++) {
                u64 a = pack_dup(avv[e2]);
                const u64* w = (const u64*)
                    &smf[(OFF_W1P >> 2) + (k4 * 4 + e2) * 128 + cg * 16];
                #pragma unroll
                for (int e = 0; e < 8; e++) acc[e] = fma2(a, w[e], acc[e]);
            }
        }
        int m16 = r >> 4, half = (r >> 3) & 1, lrow = r & 7;
        #pragma unroll
        for (int e = 0; e < 8; e++) {
            int nf1 = cg * 2 + (e >> 2);
            int ln  = lrow * 4 + (e & 3);
            float lo_, hi_;
            unpack2(acc[e], lo_, hi_);
            *(float2*)(smem + OFF_PACC +
                       (size_t)(((m16 * 16 + nf1) * 32 + ln) * 16) + half * 8)
                = make_float2(lo_, hi_);
        }
    }
    __syncthreads();

    // -------- phase C: W2 -> fragment fp16 hi/lo (overwrites W1P) ----------
    for (int i = tid; i < 4096; i += kThreads) {
        int t  = i & 31, nf = (i >> 5) & 7, kb = (i >> 8) & 7, c2 = (i >> 11) & 1;
        int gg = t >> 2, qq = t & 3;
        int n  = c2 * 64 + nf * 8 + gg;
        int k0 = kb * 16 + qq * 2;
        float w00 = W2[(size_t)k0 * 128 + n];
        float w01 = W2[(size_t)(k0 + 1) * 128 + n];
        float w10 = W2[(size_t)(k0 + 8) * 128 + n];
        float w11 = W2[(size_t)(k0 + 9) * 128 + n];
        u32 h0, l0, h1v, l1v;
        split2(w00, w01, h0, l0);
        split2(w10, w11, h1v, l1v);
        ulonglong2 e;
        e.x = ((u64)h1v << 32) | h0;
        e.y = ((u64)l1v << 32) | l0;
        *(ulonglong2*)(smem + OFF_BFRAG +
                       (size_t)(((c2 * 8 + kb) * 8 + nf) * 32 + t) * 16) = e;
    }
    // -------- phase C2: W1e rows 64..71 -> k8 B-frags [hi u32 | lo u32] ----
    for (int i = tid; i < 512; i += kThreads) {
        int t = i & 31, nf = i >> 5;        // nf1 0..15
        int gg = t >> 2, qq = t & 3;
        int n  = nf * 8 + gg;
        int k0 = qq * 2;
        float w00 = W1[(size_t)(64 + k0) * 128 + n];
        float w01 = W1[(size_t)(64 + k0 + 1) * 128 + n];
        u32 h, l;
        split2(w00, w01, h, l);
        *(u64*)(smem + OFF_W1EB + (size_t)(nf * 32 + t) * 8) =
            ((u64)l << 32) | h;
    }
    __syncthreads();

    const float b3v = __ldg(&b3[0]);
    const bool envThread = (ch == 0) && (lane < 16);
    const int  myRow = mbW * 16 + lane;           // valid when envThread
    float ego_v = 0.f, ego_x = 0.f, act_c = 0.f;  // carry in envThreads

    // ---- prefetch idm/merg for t=0 ----
    float4 pf_a0 = make_float4(0.f, 0.f, 0.f, 0.f);
    float pf_s4 = 0.f, pf_s5 = 0.f, pf_s11 = 0.f;
    float pf_m0 = 0.f, pf_m1 = 0.f, pf_m2 = 0.f;
    if (envThread) {
        const float* sp = idm + (size_t)(rowBase + myRow) * (kT * 12);
        pf_a0 = __ldg((const float4*)sp);
        float2 s45 = __ldg((const float2*)(sp + 4));
        pf_s4 = s45.x; pf_s5 = s45.y;
        pf_s11 = __ldg(sp + 11);
        const float* mp = merg + (size_t)(rowBase + myRow) * (kT * 3);
        pf_m0 = __ldg(mp); pf_m1 = __ldg(mp + 1); pf_m2 = __ldg(mp + 2);
    }

    // ================= timestep loop (pair-local pipeline) =================
    for (int t = 0; t < kT; t++) {
        // ---- env features (pair-private rows) ----
        if (envThread) {
            if (t == 0) { ego_v = pf_a0.x; ego_x = pf_a0.w; }
            else {
                ego_v = fmaf(act_c, 0.1f, ego_v);
                ego_x = ego_x + ego_v * 0.1f + act_c * 0.005f;
            }
            float ev[6];
            ev[0] = ego_v;
            ev[1] = pf_a0.y;
            ev[2] = ego_v - pf_a0.y;
            ev[3] = pf_s4 - ego_x;
            ev[4] = (ego_v - pf_a0.z) * pf_s11;
            ev[5] = (pf_s5 - ego_x) * pf_s11 + (1.0f - pf_s11) * 100.0f;
            #pragma unroll
            for (int j = 0; j < 6; j++)
                smf[(OFF_ENV >> 2) + myRow * 13 + j] =
                    (ev[j] - smf[(OFF_SC >> 2) + j]) * smf[(OFF_SC >> 2) + 8 + j];
            smf[(OFF_ENV >> 2) + myRow * 13 + 6] = pf_m0;
            smf[(OFF_ENV >> 2) + myRow * 13 + 7] = pf_m1;
            smf[(OFF_ENV >> 2) + myRow * 13 + 8] = pf_m2;
        }
        BAR_PAIR(barId);

        // ---- prefetch t+1 (hidden under the mma phase) ----
        if (envThread && t + 1 < kT) {
            const float* sp = idm + (size_t)(rowBase + myRow) * (kT * 12) +
                              (t + 1) * 12;
            pf_a0 = __ldg((const float4*)sp);
            float2 s45 = __ldg((const float2*)(sp + 4));
            pf_s4 = s45.x; pf_s5 = s45.y;
            pf_s11 = __ldg(sp + 11);
            const float* mp = merg + (size_t)(rowBase + myRow) * (kT * 3) +
                              (t + 1) * 3;
            pf_m0 = __ldg(mp); pf_m1 = __ldg(mp + 1); pf_m2 = __ldg(mp + 2);
        }

        // ---- env A-fragments (k8) + feature-8 scalars ----
        u32 ehi[2], elo[2];
        float e8v[2];
        #pragma unroll
        for (int p = 0; p < 2; p++) {
            int rr = mbW * 16 + p * 8 + g;
            const float* ep = &smf[(OFF_ENV >> 2) + rr * 13];
            split2(ep[2 * q], ep[2 * q + 1], ehi[p], elo[p]);
            e8v[p] = ep[8];
        }

        float d[8][4];
        #pragma unroll
        for (int nf = 0; nf < 8; nf++)
            d[nf][0] = d[nf][1] = d[nf][2] = d[nf][3] = 0.f;

        // GEMM1 (k8) for a k-block: both nfo chains + exact feature-8 FMA
        auto gemm1_mma = [&](int kb, float dd[2][4]) {
            int nf1 = kb * 2;
            float4 pv0 = *(const float4*)(smem + OFF_PACC +
                (size_t)(((mbW * 16 + nf1) * 32 + lane) * 16));
            float4 pv1 = *(const float4*)(smem + OFF_PACC +
                (size_t)(((mbW * 16 + nf1 + 1) * 32 + lane) * 16));
            u64 bA = *(const u64*)(smem + OFF_W1EB +
                (size_t)((nf1 * 32 + lane) * 8));
            u64 bB = *(const u64*)(smem + OFF_W1EB +
                (size_t)(((nf1 + 1) * 32 + lane) * 8));
            float2 wA = *(const float2*)(smem + OFF_W72 + (nf1 * 4 + q) * 8);
            float2 wB = *(const float2*)(smem + OFF_W72 + ((nf1 + 1) * 4 + q) * 8);
            dd[0][0] = fmaf(e8v[0], wA.x, pv0.x);
            dd[0][1] = fmaf(e8v[0], wA.y, pv0.y);
            dd[0][2] = fmaf(e8v[1], wA.x, pv0.z);
            dd[0][3] = fmaf(e8v[1], wA.y, pv0.w);
            dd[1][0] = fmaf(e8v[0], wB.x, pv1.x);
            dd[1][1] = fmaf(e8v[0], wB.y, pv1.y);
            dd[1][2] = fmaf(e8v[1], wB.x, pv1.z);
            dd[1][3] = fmaf(e8v[1], wB.y, pv1.w);
            u32 hA = (u32)bA, lA = (u32)(bA >> 32);
            u32 hB = (u32)bB, lB = (u32)(bB >> 32);
            mma1688(dd[0], ehi[0], ehi[1], hA);
            mma1688(dd[1], ehi[0], ehi[1], hB);
            mma1688(dd[0], elo[0], elo[1], hA);   // lo*hi
            mma1688(dd[1], elo[0], elo[1], hB);
            mma1688(dd[0], ehi[0], ehi[1], lA);   // hi*lo
            mma1688(dd[1], ehi[0], ehi[1], lB);
        };
        auto gemm1_split = [&](const float dd[2][4], u32 Ah[4], u32 Al[4]) {
            #pragma unroll
            for (int nfo = 0; nfo < 2; nfo++) {
                u32 h01, l01, h23, l23;
                split2(fmaxf(dd[nfo][0], 0.f), fmaxf(dd[nfo][1], 0.f), h01, l01);
                split2(fmaxf(dd[nfo][2], 0.f), fmaxf(dd[nfo][3], 0.f), h23, l23);
                Ah[nfo * 2 + 0] = h01;  Al[nfo * 2 + 0] = l01;
                Ah[nfo * 2 + 1] = h23;  Al[nfo * 2 + 1] = l23;
            }
        };

        u32 Ah[2][4], Al[2][4];
        float dd[2][4];
        gemm1_mma(0, dd);
        gemm1_split(dd, Ah[0], Al[0]);

        #pragma unroll
        for (int kb = 0; kb < 8; kb++) {
            const int cur = kb & 1, nxt = cur ^ 1;
            float ddn[2][4];
            if (kb < 7) gemm1_mma(kb + 1, ddn);   // overlap with GEMM2 below
            const char* bfp = smem + OFF_BFRAG +
                              (size_t)((ch * 8 + kb) * 8) * 512 + lane * 16;
            #pragma unroll
            for (int nf2 = 0; nf2 < 4; nf2++) {   // nf pairs, interleaved issue
                const int nA = nf2 * 2, nB = nA + 1;
                ulonglong2 bfA = *(const ulonglong2*)(bfp + nA * 512);
                ulonglong2 bfB = *(const ulonglong2*)(bfp + nB * 512);
                u32 hA0 = (u32)bfA.x, hA1 = (u32)(bfA.x >> 32);
                u32 lA0 = (u32)bfA.y, lA1 = (u32)(bfA.y >> 32);
                u32 hB0 = (u32)bfB.x, hB1 = (u32)(bfB.x >> 32);
                u32 lB0 = (u32)bfB.y, lB1 = (u32)(bfB.y >> 32);
                mma16816(d[nA], Ah[cur][0], Ah[cur][1], Ah[cur][2], Ah[cur][3],
                         hA0, hA1);
                mma16816(d[nB], Ah[cur][0], Ah[cur][1], Ah[cur][2], Ah[cur][3],
                         hB0, hB1);
                mma16816(d[nA], Al[cur][0], Al[cur][1], Al[cur][2], Al[cur][3],
                         hA0, hA1);
                mma16816(d[nB], Al[cur][0], Al[cur][1], Al[cur][2], Al[cur][3],
                         hB0, hB1);
                mma16816(d[nA], Ah[cur][0], Ah[cur][1], Ah[cur][2], Ah[cur][3],
                         lA0, lA1);
                mma16816(d[nB], Ah[cur][0], Ah[cur][1], Ah[cur][2], Ah[cur][3],
                         lB0, lB1);
            }
            if (kb < 7) gemm1_split(ddn, Ah[nxt], Al[nxt]);
        }

        // ---- epilogue: relu(D + b2) . W3 ----
        float s0 = 0.f, s1 = 0.f;
        #pragma unroll
        for (int nf = 0; nf < 8; nf++) {
            float4 bw = *(const float4*)(smem + OFF_BW +
                                         (ch * 32 + nf * 4 + q) * 16);
            s0 += fmaxf(d[nf][0] + bw.x, 0.f) * bw.z +
                  fmaxf(d[nf][1] + bw.y, 0.f) * bw.w;
            s1 += fmaxf(d[nf][2] + bw.x, 0.f) * bw.z +
                  fmaxf(d[nf][3] + bw.y, 0.f) * bw.w;
        }
        s0 += __shfl_xor_sync(0xFFFFFFFFu, s0, 1);
        s0 += __shfl_xor_sync(0xFFFFFFFFu, s0, 2);
        s1 += __shfl_xor_sync(0xFFFFFFFFu, s1, 1);
        s1 += __shfl_xor_sync(0xFFFFFFFFu, s1, 2);
        if (q == 0) {
            smf[(OFF_PART >> 2) + mbW * 32 + ch * 16 + g]     = s0;
            smf[(OFF_PART >> 2) + mbW * 32 + ch * 16 + g + 8] = s1;
        }
        BAR_PAIR(barId);

        if (envThread) {
            float a = smf[(OFF_PART >> 2) + mbW * 32 + lane] +
                      smf[(OFF_PART >> 2) + mbW * 32 + 16 + lane] + b3v;
            act_c = a;
            out[(size_t)(rowBase + myRow) * kT + t] = a;
        }
        // env(t+1)/PART reuse guarded by the two pair barriers per step.
    }
}

extern "C" void kernel_launch(void* const* d_in, const int* in_sizes, int n_in,
                              void* d_out, int out_size)
{
    (void)in_sizes; (void)n_in; (void)out_size;
    const float* proj  = (const float*)d_in[0];
    const float* idm   = (const float*)d_in[1];
    const float* merg  = (const float*)d_in[2];
    const float* W1    = (const float*)d_in[3];
    const float* b1    = (const float*)d_in[4];
    const float* W2    = (const float*)d_in[5];
    const float* b2    = (const float*)d_in[6];
    const float* W3    = (const float*)d_in[7];
    const float* b3    = (const float*)d_in[8];
    const float* smean = (const float*)d_in[9];
    const float* svar  = (const float*)d_in[10];
    float* out = (float*)d_out;

    cudaFuncSetAttribute(fsim_mma, cudaFuncAttributeMaxDynamicSharedMemorySize,
                         SMEM_BYTES);
    fsim_mma<<<kB / kM, kThreads, SMEM_BYTES>>>(
        proj, idm, merg, W1, b1, W2, b2, W3, b3, smean, svar, out);
}

// round 10
// speedup vs baseline: 1.3376x; 1.2248x over previous
#include <cuda_runtime.h>
#include <cuda_fp16.h>
#include <cstddef>

// ForwardSim, fully tensorized HMMA (sm_103 baseline mma.sync).
// R10 = R9 + 2-term split for GEMM2: D = (A_hi + A_lo) @ B_hi, dropping the
// zero-mean A_hi@B_lo term (W2 fp16 rounding is RN => error cancels over
// K=128; predicted output rel_err ~5e-4 < 1e-3 gate). Cuts GEMM2 tensor work
// by 1/3 and halves B-fragment smem traffic (hi-only frags, packed per
// nf-pair: one LDS.128 feeds 4 mmas covering 16 rows x 16 cols).
// GEMM1 stays 3-term (k8 + exact fp32 feature-8 FMA). Pair-local barriers.

using u32 = unsigned int;
using u64 = unsigned long long;

namespace {
constexpr int kB = 32768, kT = 50, kH = 128, kM = 64, kThreads = 256;

constexpr int OFF_BFRAG = 0;        // 32768: W2 hi frags [ch][kb][nf2][lane] 16B
constexpr int OFF_PACC  = 32768;    // 32768: projAcc frags [m16][nf1][lane] 16B
constexpr int OFF_W1EB  = 65536;    // 4096:  W1e k8 B-frags [nf1][lane] 8B
constexpr int OFF_W72   = 69632;    // 512:   W1 row 72 natural
constexpr int OFF_ENV   = 70144;    // 3328:  64 x 13 f32 (pair-private rows)
constexpr int OFF_BW    = 73472;    // 1024:  (b2 pair, W3 pair) per col pair
constexpr int OFF_PART  = 74496;    // 512:   [mb][ch][row16] partials
constexpr int OFF_SC    = 75008;    // 64
constexpr int SMEM_BYTES = 75072;
constexpr int OFF_W1P   = 0;        // phase alias in BFRAG: W1[0:64] natural
} // namespace

__device__ __forceinline__ u64 pack_dup(float v) {
    u64 r; asm("mov.b64 %0, {%1, %1};" : "=l"(r) : "f"(v)); return r;
}
__device__ __forceinline__ u64 pack2(float a, float b) {
    u64 r; asm("mov.b64 %0, {%1, %2};" : "=l"(r) : "f"(a), "f"(b)); return r;
}
__device__ __forceinline__ void unpack2(u64 v, float& a, float& b) {
    asm("mov.b64 {%0, %1}, %2;" : "=f"(a), "=f"(b) : "l"(v));
}
__device__ __forceinline__ u64 fma2(u64 a, u64 b, u64 c) {
    u64 d; asm("fma.rn.f32x2 %0, %1, %2, %3;" : "=l"(d) : "l"(a), "l"(b), "l"(c));
    return d;
}
__device__ __forceinline__ void split2(float f0, float f1, u32& hi, u32& lo) {
    __half h0 = __float2half_rn(f0), h1 = __float2half_rn(f1);
    __half2 hh = __halves2half2(h0, h1);
    hi = reinterpret_cast<u32&>(hh);
    __half2 ll = __floats2half2_rn(f0 - __half2float(h0),
                                   f1 - __half2float(h1));
    lo = reinterpret_cast<u32&>(ll);
}
__device__ __forceinline__ u32 hi2only(float f0, float f1) {
    __half2 hh = __floats2half2_rn(f0, f1);
    return reinterpret_cast<u32&>(hh);
}
__device__ __forceinline__ void mma16816(float d[4], u32 a0, u32 a1, u32 a2,
                                         u32 a3, u32 b0, u32 b1) {
    asm volatile(
        "mma.sync.aligned.m16n8k16.row.col.f32.f16.f16.f32 "
        "{%0,%1,%2,%3}, {%4,%5,%6,%7}, {%8,%9}, {%0,%1,%2,%3};"
        : "+f"(d[0]), "+f"(d[1]), "+f"(d[2]), "+f"(d[3])
        : "r"(a0), "r"(a1), "r"(a2), "r"(a3), "r"(b0), "r"(b1));
}
__device__ __forceinline__ void mma1688(float d[4], u32 a0, u32 a1, u32 b0) {
    asm volatile(
        "mma.sync.aligned.m16n8k8.row.col.f32.f16.f16.f32 "
        "{%0,%1,%2,%3}, {%4,%5}, {%6}, {%0,%1,%2,%3};"
        : "+f"(d[0]), "+f"(d[1]), "+f"(d[2]), "+f"(d[3])
        : "r"(a0), "r"(a1), "r"(b0));
}
#define BAR_PAIR(id) asm volatile("bar.sync %0, 64;" :: "r"(id) : "memory")

__global__ void __launch_bounds__(kThreads, 2)
fsim_mma(const float* __restrict__ proj, const float* __restrict__ idm,
         const float* __restrict__ merg, const float* __restrict__ W1,
         const float* __restrict__ b1,   const float* __restrict__ W2,
         const float* __restrict__ b2,   const float* __restrict__ W3,
         const float* __restrict__ b3,   const float* __restrict__ smean,
         const float* __restrict__ svar, float* __restrict__ out)
{
    extern __shared__ char smem[];
    float* smf = (float*)smem;

    const int tid = threadIdx.x, wid = tid >> 5, lane = tid & 31;
    const int mbW = wid >> 1, ch = wid & 1, g = lane >> 2, q = lane & 3;
    const int rowBase = blockIdx.x * kM;
    const int barId = mbW + 1;

    // ---------------- phase A: stage W1[0:64] natural + tables -------------
    for (int i = tid; i < 64 * kH; i += kThreads)
        smf[(OFF_W1P >> 2) + i] = W1[i];
    if (tid < 64) {
        int c = tid * 2;
        float4 v;
        v.x = b2[c]; v.y = b2[c + 1]; v.z = W3[c]; v.w = W3[c + 1];
        *(float4*)(smem + OFF_BW + tid * 16) = v;
    }
    if (tid < 6) {
        smf[(OFF_SC >> 2) + tid]     = smean[tid];
        smf[(OFF_SC >> 2) + 8 + tid] = rsqrtf(svar[tid]);
    }
    if (tid < 128)
        smf[(OFF_W72 >> 2) + tid] = W1[(size_t)72 * 128 + tid];
    __syncthreads();

    // -------- phase B: projAcc = proj@W1[:64]+b1 -> fragment-native fp32 ---
    for (int task = tid; task < 512; task += kThreads) {
        int r = task >> 3, cg = task & 7;   // row (0..63), 16-col group
        const float* prow = proj + (size_t)(rowBase + r) * 64;
        u64 acc[8];
        #pragma unroll
        for (int e = 0; e < 8; e++)
            acc[e] = pack2(__ldg(&b1[cg * 16 + 2 * e]),
                           __ldg(&b1[cg * 16 + 2 * e + 1]));
        #pragma unroll 4
        for (int k4 = 0; k4 < 16; k4++) {
            float4 av = __ldg((const float4*)(prow + k4 * 4));
            float avv[4] = {av.x, av.y, av.z, av.w};
            #pragma unroll
            for (int e2 = 0; e2 < 4; e2++) {
                u64 a = pack_dup(avv[e2]);
                const u64* w = (const u64*)
                    &smf[(OFF_W1P >> 2) + (k4 * 4 + e2) * 128 + cg * 16];
                #pragma unroll
                for (int e = 0; e < 8; e++) acc[e] = fma2(a, w[e], acc[e]);
            }
        }
        int m16 = r >> 4, half = (r >> 3) & 1, lrow = r & 7;
        #pragma unroll
        for (int e = 0; e < 8; e++) {
            int nf1 = cg * 2 + (e >> 2);
            int ln  = lrow * 4 + (e & 3);
            float lo_, hi_;
            unpack2(acc[e], lo_, hi_);
            *(float2*)(smem + OFF_PACC +
                       (size_t)(((m16 * 16 + nf1) * 32 + ln) * 16) + half * 8)
                = make_float2(lo_, hi_);
        }
    }
    __syncthreads();

    // ---- phase C: W2 -> hi-only frags, packed per nf-pair (overwrites W1P)
    // entry (c2, kb, nf2, lane) 16B = {hA0, hA1, hB0, hB1}, A=2*nf2, B=2*nf2+1
    for (int i = tid; i < 2048; i += kThreads) {
        int t  = i & 31, nf2 = (i >> 5) & 3, kb = (i >> 7) & 7, c2 = (i >> 10) & 1;
        int gg = t >> 2, qq = t & 3;
        int k0 = kb * 16 + qq * 2;
        int nA = c2 * 64 + (nf2 * 2) * 8 + gg;
        int nB = nA + 8;
        u32 hA0 = hi2only(W2[(size_t)k0 * 128 + nA],
                          W2[(size_t)(k0 + 1) * 128 + nA]);
        u32 hA1 = hi2only(W2[(size_t)(k0 + 8) * 128 + nA],
                          W2[(size_t)(k0 + 9) * 128 + nA]);
        u32 hB0 = hi2only(W2[(size_t)k0 * 128 + nB],
                          W2[(size_t)(k0 + 1) * 128 + nB]);
        u32 hB1 = hi2only(W2[(size_t)(k0 + 8) * 128 + nB],
                          W2[(size_t)(k0 + 9) * 128 + nB]);
        ulonglong2 e;
        e.x = ((u64)hA1 << 32) | hA0;
        e.y = ((u64)hB1 << 32) | hB0;
        *(ulonglong2*)(smem + OFF_BFRAG +
                       (size_t)(((c2 * 8 + kb) * 4 + nf2) * 32 + t) * 16) = e;
    }
    // -------- phase C2: W1e rows 64..71 -> k8 B-frags [hi u32 | lo u32] ----
    for (int i = tid; i < 512; i += kThreads) {
        int t = i & 31, nf = i >> 5;        // nf1 0..15
        int gg = t >> 2, qq = t & 3;
        int n  = nf * 8 + gg;
        int k0 = qq * 2;
        float w00 = W1[(size_t)(64 + k0) * 128 + n];
        float w01 = W1[(size_t)(64 + k0 + 1) * 128 + n];
        u32 h, l;
        split2(w00, w01, h, l);
        *(u64*)(smem + OFF_W1EB + (size_t)(nf * 32 + t) * 8) =
            ((u64)l << 32) | h;
    }
    __syncthreads();

    const float b3v = __ldg(&b3[0]);
    const bool envThread = (ch == 0) && (lane < 16);
    const int  myRow = mbW * 16 + lane;           // valid when envThread
    float ego_v = 0.f, ego_x = 0.f, act_c = 0.f;  // carry in envThreads

    // ---- prefetch idm/merg for t=0 ----
    float4 pf_a0 = make_float4(0.f, 0.f, 0.f, 0.f);
    float pf_s4 = 0.f, pf_s5 = 0.f, pf_s11 = 0.f;
    float pf_m0 = 0.f, pf_m1 = 0.f, pf_m2 = 0.f;
    if (envThread) {
        const float* sp = idm + (size_t)(rowBase + myRow) * (kT * 12);
        pf_a0 = __ldg((const float4*)sp);
        float2 s45 = __ldg((const float2*)(sp + 4));
        pf_s4 = s45.x; pf_s5 = s45.y;
        pf_s11 = __ldg(sp + 11);
        const float* mp = merg + (size_t)(rowBase + myRow) * (kT * 3);
        pf_m0 = __ldg(mp); pf_m1 = __ldg(mp + 1); pf_m2 = __ldg(mp + 2);
    }

    // ================= timestep loop (pair-local pipeline) =================
    for (int t = 0; t < kT; t++) {
        // ---- env features (pair-private rows) ----
        if (envThread) {
            if (t == 0) { ego_v = pf_a0.x; ego_x = pf_a0.w; }
            else {
                ego_v = fmaf(act_c, 0.1f, ego_v);
                ego_x = ego_x + ego_v * 0.1f + act_c * 0.005f;
            }
            float ev[6];
            ev[0] = ego_v;
            ev[1] = pf_a0.y;
            ev[2] = ego_v - pf_a0.y;
            ev[3] = pf_s4 - ego_x;
            ev[4] = (ego_v - pf_a0.z) * pf_s11;
            ev[5] = (pf_s5 - ego_x) * pf_s11 + (1.0f - pf_s11) * 100.0f;
            #pragma unroll
            for (int j = 0; j < 6; j++)
                smf[(OFF_ENV >> 2) + myRow * 13 + j] =
                    (ev[j] - smf[(OFF_SC >> 2) + j]) * smf[(OFF_SC >> 2) + 8 + j];
            smf[(OFF_ENV >> 2) + myRow * 13 + 6] = pf_m0;
            smf[(OFF_ENV >> 2) + myRow * 13 + 7] = pf_m1;
            smf[(OFF_ENV >> 2) + myRow * 13 + 8] = pf_m2;
        }
        BAR_PAIR(barId);

        // ---- prefetch t+1 (hidden under the mma phase) ----
        if (envThread && t + 1 < kT) {
            const float* sp = idm + (size_t)(rowBase + myRow) * (kT * 12) +
                              (t + 1) * 12;
            pf_a0 = __ldg((const float4*)sp);
            float2 s45 = __ldg((const float2*)(sp + 4));
            pf_s4 = s45.x; pf_s5 = s45.y;
            pf_s11 = __ldg(sp + 11);
            const float* mp = merg + (size_t)(rowBase + myRow) * (kT * 3) +
                              (t + 1) * 3;
            pf_m0 = __ldg(mp); pf_m1 = __ldg(mp + 1); pf_m2 = __ldg(mp + 2);
        }

        // ---- env A-fragments (k8) + feature-8 scalars ----
        u32 ehi[2], elo[2];
        float e8v[2];
        #pragma unroll
        for (int p = 0; p < 2; p++) {
            int rr = mbW * 16 + p * 8 + g;
            const float* ep = &smf[(OFF_ENV >> 2) + rr * 13];
            split2(ep[2 * q], ep[2 * q + 1], ehi[p], elo[p]);
            e8v[p] = ep[8];
        }

        float d[8][4];
        #pragma unroll
        for (int nf = 0; nf < 8; nf++)
            d[nf][0] = d[nf][1] = d[nf][2] = d[nf][3] = 0.f;

        // GEMM1 (k8, 3-term) for a k-block + exact feature-8 FMA
        auto gemm1_mma = [&](int kb, float dd[2][4]) {
            int nf1 = kb * 2;
            float4 pv0 = *(const float4*)(smem + OFF_PACC +
                (size_t)(((mbW * 16 + nf1) * 32 + lane) * 16));
            float4 pv1 = *(const float4*)(smem + OFF_PACC +
                (size_t)(((mbW * 16 + nf1 + 1) * 32 + lane) * 16));
            u64 bA = *(const u64*)(smem + OFF_W1EB +
                (size_t)((nf1 * 32 + lane) * 8));
            u64 bB = *(const u64*)(smem + OFF_W1EB +
                (size_t)(((nf1 + 1) * 32 + lane) * 8));
            float2 wA = *(const float2*)(smem + OFF_W72 + (nf1 * 4 + q) * 8);
            float2 wB = *(const float2*)(smem + OFF_W72 + ((nf1 + 1) * 4 + q) * 8);
            dd[0][0] = fmaf(e8v[0], wA.x, pv0.x);
            dd[0][1] = fmaf(e8v[0], wA.y, pv0.y);
            dd[0][2] = fmaf(e8v[1], wA.x, pv0.z);
            dd[0][3] = fmaf(e8v[1], wA.y, pv0.w);
            dd[1][0] = fmaf(e8v[0], wB.x, pv1.x);
            dd[1][1] = fmaf(e8v[0], wB.y, pv1.y);
            dd[1][2] = fmaf(e8v[1], wB.x, pv1.z);
            dd[1][3] = fmaf(e8v[1], wB.y, pv1.w);
            u32 hA = (u32)bA, lA = (u32)(bA >> 32);
            u32 hB = (u32)bB, lB = (u32)(bB >> 32);
            mma1688(dd[0], ehi[0], ehi[1], hA);
            mma1688(dd[1], ehi[0], ehi[1], hB);
            mma1688(dd[0], elo[0], elo[1], hA);   // lo*hi
            mma1688(dd[1], elo[0], elo[1], hB);
            mma1688(dd[0], ehi[0], ehi[1], lA);   // hi*lo
            mma1688(dd[1], ehi[0], ehi[1], lB);
        };
        auto gemm1_split = [&](const float dd[2][4], u32 Ah[4], u32 Al[4]) {
            #pragma unroll
            for (int nfo = 0; nfo < 2; nfo++) {
                u32 h01, l01, h23, l23;
                split2(fmaxf(dd[nfo][0], 0.f), fmaxf(dd[nfo][1], 0.f), h01, l01);
                split2(fmaxf(dd[nfo][2], 0.f), fmaxf(dd[nfo][3], 0.f), h23, l23);
                Ah[nfo * 2 + 0] = h01;  Al[nfo * 2 + 0] = l01;
                Ah[nfo * 2 + 1] = h23;  Al[nfo * 2 + 1] = l23;
            }
        };

        u32 Ah[2][4], Al[2][4];
        float dd[2][4];
        gemm1_mma(0, dd);
        gemm1_split(dd, Ah[0], Al[0]);

        #pragma unroll
        for (int kb = 0; kb < 8; kb++) {
            const int cur = kb & 1, nxt = cur ^ 1;
            float ddn[2][4];
            if (kb < 7) gemm1_mma(kb + 1, ddn);   // overlap with GEMM2 below
            const char* bfp = smem + OFF_BFRAG +
                              (size_t)((ch * 8 + kb) * 4) * 512 + lane * 16;
            #pragma unroll
            for (int nf2 = 0; nf2 < 4; nf2++) {   // nf pairs: 1 LDS.128, 4 mmas
                const int nA = nf2 * 2, nB = nA + 1;
                ulonglong2 bf = *(const ulonglong2*)(bfp + nf2 * 512);
                u32 hA0 = (u32)bf.x, hA1 = (u32)(bf.x >> 32);
                u32 hB0 = (u32)bf.y, hB1 = (u32)(bf.y >> 32);
                mma16816(d[nA], Ah[cur][0], Ah[cur][1], Ah[cur][2], Ah[cur][3],
                         hA0, hA1);                               // hi*hi
                mma16816(d[nB], Ah[cur][0], Ah[cur][1], Ah[cur][2], Ah[cur][3],
                         hB0, hB1);
                mma16816(d[nA], Al[cur][0], Al[cur][1], Al[cur][2], Al[cur][3],
                         hA0, hA1);                               // lo*hi
                mma16816(d[nB], Al[cur][0], Al[cur][1], Al[cur][2], Al[cur][3],
                         hB0, hB1);
            }
            if (kb < 7) gemm1_split(ddn, Ah[nxt], Al[nxt]);
        }

        // ---- epilogue: relu(D + b2) . W3 ----
        float s0 = 0.f, s1 = 0.f;
        #pragma unroll
        for (int nf = 0; nf < 8; nf++) {
            float4 bw = *(const float4*)(smem + OFF_BW +
                                         (ch * 32 + nf * 4 + q) * 16);
            s0 += fmaxf(d[nf][0] + bw.x, 0.f) * bw.z +
                  fmaxf(d[nf][1] + bw.y, 0.f) * bw.w;
            s1 += fmaxf(d[nf][2] + bw.x, 0.f) * bw.z +
                  fmaxf(d[nf][3] + bw.y, 0.f) * bw.w;
        }
        s0 += __shfl_xor_sync(0xFFFFFFFFu, s0, 1);
        s0 += __shfl_xor_sync(0xFFFFFFFFu, s0, 2);
        s1 += __shfl_xor_sync(0xFFFFFFFFu, s1, 1);
        s1 += __shfl_xor_sync(0xFFFFFFFFu, s1, 2);
        if (q == 0) {
            smf[(OFF_PART >> 2) + mbW * 32 + ch * 16 + g]     = s0;
            smf[(OFF_PART >> 2) + mbW * 32 + ch * 16 + g + 8] = s1;
        }
        BAR_PAIR(barId);

        if (envThread) {
            float a = smf[(OFF_PART >> 2) + mbW * 32 + lane] +
                      smf[(OFF_PART >> 2) + mbW * 32 + 16 + lane] + b3v;
            act_c = a;
            out[(size_t)(rowBase + myRow) * kT + t] = a;
        }
        // env(t+1)/PART reuse guarded by the two pair barriers per step.
    }
}

extern "C" void kernel_launch(void* const* d_in, const int* in_sizes, int n_in,
                              void* d_out, int out_size)
{
    (void)in_sizes; (void)n_in; (void)out_size;
    const float* proj  = (const float*)d_in[0];
    const float* idm   = (const float*)d_in[1];
    const float* merg  = (const float*)d_in[2];
    const float* W1    = (const float*)d_in[3];
    const float* b1    = (const float*)d_in[4];
    const float* W2    = (const float*)d_in[5];
    const float* b2    = (const float*)d_in[6];
    const float* W3    = (const float*)d_in[7];
    const float* b3    = (const float*)d_in[8];
    const float* smean = (const float*)d_in[9];
    const float* svar  = (const float*)d_in[10];
    float* out = (float*)d_out;

    cudaFuncSetAttribute(fsim_mma, cudaFuncAttributeMaxDynamicSharedMemorySize,
                         SMEM_BYTES);
    fsim_mma<<<kB / kM, kThreads, SMEM_BYTES>>>(
        proj, idm, merg, W1, b1, W2, b2, W3, b3, smean, svar, out);
}

// round 11
// speedup vs baseline: 1.3766x; 1.0291x over previous
#include <cuda_runtime.h>
#include <cuda_fp16.h>
#include <cstddef>

// ForwardSim, fully tensorized HMMA (sm_103 baseline mma.sync).
// R11: one warp owns 16 rows x 128 cols for all 50 steps (kM=128, grid 256,
// 2 CTA/SM). GEMM1 + projAcc loads deduplicated (once per 16 rows), and the
// whole timestep pipeline is warp-local: env computed per-lane from gmem
// (redundant over q), carry + act live in registers (post-shfl s0/s1 are the
// lane's own rows), NO barriers / NO smem state in the hot loop.
// GEMM2: 2-term fp16 split (A hi+lo, B hi-only). GEMM1: k8 3-term + exact
// fp32 feature-8 FMA.

using u32 = unsigned int;
using u64 = unsigned long long;

namespace {
constexpr int kB = 32768, kT = 50, kH = 128, kM = 128, kThreads = 256;

constexpr int OFF_BFRAG = 0;        // 32768: W2 hi frags [kb][nf2][lane] 16B
constexpr int OFF_PACC  = 32768;    // 65536: projAcc frags [m16][nf1][lane] 16B
constexpr int OFF_W1EB  = 98304;    // 4096:  W1e k8 B-frags [nf1][lane] 8B
constexpr int OFF_W72   = 102400;   // 512:   W1 row 72 natural
constexpr int OFF_BW    = 102912;   // 1024:  (b2 pair, W3 pair) per col pair
constexpr int SMEM_BYTES = 103936;
constexpr int OFF_W1P   = 0;        // phase alias in BFRAG: W1[0:64] natural
} // namespace

__device__ __forceinline__ u64 pack_dup(float v) {
    u64 r; asm("mov.b64 %0, {%1, %1};" : "=l"(r) : "f"(v)); return r;
}
__device__ __forceinline__ u64 pack2(float a, float b) {
    u64 r; asm("mov.b64 %0, {%1, %2};" : "=l"(r) : "f"(a), "f"(b)); return r;
}
__device__ __forceinline__ void unpack2(u64 v, float& a, float& b) {
    asm("mov.b64 {%0, %1}, %2;" : "=f"(a), "=f"(b) : "l"(v));
}
__device__ __forceinline__ u64 fma2(u64 a, u64 b, u64 c) {
    u64 d; asm("fma.rn.f32x2 %0, %1, %2, %3;" : "=l"(d) : "l"(a), "l"(b), "l"(c));
    return d;
}
__device__ __forceinline__ void split2(float f0, float f1, u32& hi, u32& lo) {
    __half h0 = __float2half_rn(f0), h1 = __float2half_rn(f1);
    __half2 hh = __halves2half2(h0, h1);
    hi = reinterpret_cast<u32&>(hh);
    __half2 ll = __floats2half2_rn(f0 - __half2float(h0),
                                   f1 - __half2float(h1));
    lo = reinterpret_cast<u32&>(ll);
}
__device__ __forceinline__ u32 hi2only(float f0, float f1) {
    __half2 hh = __floats2half2_rn(f0, f1);
    return reinterpret_cast<u32&>(hh);
}
__device__ __forceinline__ void mma16816(float d[4], u32 a0, u32 a1, u32 a2,
                                         u32 a3, u32 b0, u32 b1) {
    asm volatile(
        "mma.sync.aligned.m16n8k16.row.col.f32.f16.f16.f32 "
        "{%0,%1,%2,%3}, {%4,%5,%6,%7}, {%8,%9}, {%0,%1,%2,%3};"
        : "+f"(d[0]), "+f"(d[1]), "+f"(d[2]), "+f"(d[3])
        : "r"(a0), "r"(a1), "r"(a2), "r"(a3), "r"(b0), "r"(b1));
}
__device__ __forceinline__ void mma1688(float d[4], u32 a0, u32 a1, u32 b0) {
    asm volatile(
        "mma.sync.aligned.m16n8k8.row.col.f32.f16.f16.f32 "
        "{%0,%1,%2,%3}, {%4,%5}, {%6}, {%0,%1,%2,%3};"
        : "+f"(d[0]), "+f"(d[1]), "+f"(d[2]), "+f"(d[3])
        : "r"(a0), "r"(a1), "r"(b0));
}

__global__ void __launch_bounds__(kThreads, 2)
fsim_mma(const float* __restrict__ proj, const float* __restrict__ idm,
         const float* __restrict__ merg, const float* __restrict__ W1,
         const float* __restrict__ b1,   const float* __restrict__ W2,
         const float* __restrict__ b2,   const float* __restrict__ W3,
         const float* __restrict__ b3,   const float* __restrict__ smean,
         const float* __restrict__ svar, float* __restrict__ out)
{
    extern __shared__ char smem[];
    float* smf = (float*)smem;

    const int tid = threadIdx.x, w = tid >> 5, lane = tid & 31;
    const int g = lane >> 2, q = lane & 3;
    const int rowBase = blockIdx.x * kM;

    // ---------------- phase A: stage W1[0:64] natural + tables -------------
    for (int i = tid; i < 64 * kH; i += kThreads)
        smf[(OFF_W1P >> 2) + i] = W1[i];
    if (tid < 64) {
        int c = tid * 2;
        float4 v;
        v.x = b2[c]; v.y = b2[c + 1]; v.z = W3[c]; v.w = W3[c + 1];
        *(float4*)(smem + OFF_BW + tid * 16) = v;
    }
    if (tid < 128)
        smf[(OFF_W72 >> 2) + tid] = W1[(size_t)72 * 128 + tid];
    __syncthreads();

    // -------- phase B: projAcc = proj@W1[:64]+b1 -> fragment-native fp32 ---
    for (int task = tid; task < 1024; task += kThreads) {
        int r = task >> 3, cg = task & 7;   // row (0..127), 16-col group
        const float* prow = proj + (size_t)(rowBase + r) * 64;
        u64 acc[8];
        #pragma unroll
        for (int e = 0; e < 8; e++)
            acc[e] = pack2(__ldg(&b1[cg * 16 + 2 * e]),
                           __ldg(&b1[cg * 16 + 2 * e + 1]));
        #pragma unroll 4
        for (int k4 = 0; k4 < 16; k4++) {
            float4 av = __ldg((const float4*)(prow + k4 * 4));
            float avv[4] = {av.x, av.y, av.z, av.w};
            #pragma unroll
            for (int e2 = 0; e2 < 4; e2++) {
                u64 a = pack_dup(avv[e2]);
                const u64* ww = (const u64*)
                    &smf[(OFF_W1P >> 2) + (k4 * 4 + e2) * 128 + cg * 16];
                #pragma unroll
                for (int e = 0; e < 8; e++) acc[e] = fma2(a, ww[e], acc[e]);
            }
        }
        int m16 = r >> 4, half = (r >> 3) & 1, lrow = r & 7;
        #pragma unroll
        for (int e = 0; e < 8; e++) {
            int nf1 = cg * 2 + (e >> 2);
            int ln  = lrow * 4 + (e & 3);
            float lo_, hi_;
            unpack2(acc[e], lo_, hi_);
            *(float2*)(smem + OFF_PACC +
                       (size_t)(((m16 * 16 + nf1) * 32 + ln) * 16) + half * 8)
                = make_float2(lo_, hi_);
        }
    }
    __syncthreads();

    // ---- phase C: W2 -> hi-only frags packed per nf-pair (overwrites W1P) -
    for (int i = tid; i < 2048; i += kThreads) {
        int t  = i & 31, nf2 = (i >> 5) & 7, kb = (i >> 8) & 7;
        int gg = t >> 2, qq = t & 3;
        int k0 = kb * 16 + qq * 2;
        int nA = nf2 * 16 + gg;
        int nB = nA + 8;
        u32 hA0 = hi2only(W2[(size_t)k0 * 128 + nA],
                          W2[(size_t)(k0 + 1) * 128 + nA]);
        u32 hA1 = hi2only(W2[(size_t)(k0 + 8) * 128 + nA],
                          W2[(size_t)(k0 + 9) * 128 + nA]);
        u32 hB0 = hi2only(W2[(size_t)k0 * 128 + nB],
                          W2[(size_t)(k0 + 1) * 128 + nB]);
        u32 hB1 = hi2only(W2[(size_t)(k0 + 8) * 128 + nB],
                          W2[(size_t)(k0 + 9) * 128 + nB]);
        ulonglong2 e;
        e.x = ((u64)hA1 << 32) | hA0;
        e.y = ((u64)hB1 << 32) | hB0;
        *(ulonglong2*)(smem + OFF_BFRAG +
                       (size_t)((kb * 8 + nf2) * 32 + t) * 16) = e;
    }
    // -------- phase C2: W1e rows 64..71 -> k8 B-frags [hi u32 | lo u32] ----
    for (int i = tid; i < 512; i += kThreads) {
        int t = i & 31, nf = i >> 5;        // nf1 0..15
        int gg = t >> 2, qq = t & 3;
        int n  = nf * 8 + gg;
        int k0 = qq * 2;
        float w00 = W1[(size_t)(64 + k0) * 128 + n];
        float w01 = W1[(size_t)(64 + k0 + 1) * 128 + n];
        u32 h, l;
        split2(w00, w01, h, l);
        *(u64*)(smem + OFF_W1EB + (size_t)(nf * 32 + t) * 8) =
            ((u64)l << 32) | h;
    }
    __syncthreads();

    // ---------------- per-lane constants ----------------
    const float b3v = __ldg(&b3[0]);
    const int gr0 = rowBase + w * 16 + g;      // this lane's two rows
    const int gr1 = gr0 + 8;
    // scaler consts for features j = 2q, 2q+1 (q==3 -> mc passthrough)
    float scm0 = 0.f, scm1 = 0.f, sci0 = 1.f, sci1 = 1.f;
    if (q < 3) {
        scm0 = __ldg(&smean[2 * q]);
        scm1 = __ldg(&smean[2 * q + 1]);
        sci0 = rsqrtf(__ldg(&svar[2 * q]));
        sci1 = rsqrtf(__ldg(&svar[2 * q + 1]));
    }

    // carry + prefetch (per lane, both rows; redundant over q — no comms)
    float egv[2], egx[2], act[2] = {0.f, 0.f};
    float4 pa[2];
    float ps4[2], ps5[2], ps11[2], pm0[2], pm1[2], pm2[2];
    #pragma unroll
    for (int i = 0; i < 2; i++) {
        int gr = (i == 0) ? gr0 : gr1;
        const float* sp = idm + (size_t)gr * (kT * 12);
        pa[i] = __ldg((const float4*)sp);
        float2 s45 = __ldg((const float2*)(sp + 4));
        ps4[i] = s45.x; ps5[i] = s45.y;
        ps11[i] = __ldg(sp + 11);
        const float* mp = merg + (size_t)gr * (kT * 3);
        pm0[i] = __ldg(mp); pm1[i] = __ldg(mp + 1); pm2[i] = __ldg(mp + 2);
    }

    // ================= timestep loop (warp-local, no barriers) =============
    for (int t = 0; t < kT; t++) {
        // ---- env features + A-fragments, in registers ----
        u32 ehi[2], elo[2];
        float e8v[2];
        #pragma unroll
        for (int i = 0; i < 2; i++) {
            if (t == 0) { egv[i] = pa[i].x; egx[i] = pa[i].w; }
            else {
                egv[i] = fmaf(act[i], 0.1f, egv[i]);
                egx[i] = egx[i] + egv[i] * 0.1f + act[i] * 0.005f;
            }
            float f0 = egv[i];
            float f1 = pa[i].y;
            float f2 = egv[i] - pa[i].y;
            float f3 = ps4[i] - egx[i];
            float f4 = (egv[i] - pa[i].z) * ps11[i];
            float f5 = (ps5[i] - egx[i]) * ps11[i] + (1.0f - ps11[i]) * 100.0f;
            float fa, fb;
            if      (q == 0) { fa = f0; fb = f1; }
            else if (q == 1) { fa = f2; fb = f3; }
            else if (q == 2) { fa = f4; fb = f5; }
            else             { fa = pm0[i]; fb = pm1[i]; }
            fa = (fa - scm0) * sci0;
            fb = (fb - scm1) * sci1;
            split2(fa, fb, ehi[i], elo[i]);
            e8v[i] = pm2[i];
        }

        // ---- prefetch t+1 (hidden under the mma phase) ----
        if (t + 1 < kT) {
            #pragma unroll
            for (int i = 0; i < 2; i++) {
                int gr = (i == 0) ? gr0 : gr1;
                const float* sp = idm + (size_t)gr * (kT * 12) + (t + 1) * 12;
                pa[i] = __ldg((const float4*)sp);
                float2 s45 = __ldg((const float2*)(sp + 4));
                ps4[i] = s45.x; ps5[i] = s45.y;
                ps11[i] = __ldg(sp + 11);
                const float* mp = merg + (size_t)gr * (kT * 3) + (t + 1) * 3;
                pm0[i] = __ldg(mp); pm1[i] = __ldg(mp + 1); pm2[i] = __ldg(mp + 2);
            }
        }

        float d[16][4];
        #pragma unroll
        for (int nf = 0; nf < 16; nf++)
            d[nf][0] = d[nf][1] = d[nf][2] = d[nf][3] = 0.f;

        for (int kb = 0; kb < 8; kb++) {
            // ---- GEMM1 (k8, 3-term) + exact feature-8 FMA ----
            int nf1 = kb * 2;
            float4 pv0 = *(const float4*)(smem + OFF_PACC +
                (size_t)(((w * 16 + nf1) * 32 + lane) * 16));
            float4 pv1 = *(const float4*)(smem + OFF_PACC +
                (size_t)(((w * 16 + nf1 + 1) * 32 + lane) * 16));
            u64 bA = *(const u64*)(smem + OFF_W1EB +
                (size_t)((nf1 * 32 + lane) * 8));
            u64 bB = *(const u64*)(smem + OFF_W1EB +
                (size_t)(((nf1 + 1) * 32 + lane) * 8));
            float2 wA = *(const float2*)(smem + OFF_W72 + (nf1 * 4 + q) * 8);
            float2 wB = *(const float2*)(smem + OFF_W72 + ((nf1 + 1) * 4 + q) * 8);
            float dd[2][4];
            dd[0][0] = fmaf(e8v[0], wA.x, pv0.x);
            dd[0][1] = fmaf(e8v[0], wA.y, pv0.y);
            dd[0][2] = fmaf(e8v[1], wA.x, pv0.z);
            dd[0][3] = fmaf(e8v[1], wA.y, pv0.w);
            dd[1][0] = fmaf(e8v[0], wB.x, pv1.x);
            dd[1][1] = fmaf(e8v[0], wB.y, pv1.y);
            dd[1][2] = fmaf(e8v[1], wB.x, pv1.z);
            dd[1][3] = fmaf(e8v[1], wB.y, pv1.w);
            u32 hA = (u32)bA, lA = (u32)(bA >> 32);
            u32 hB = (u32)bB, lB = (u32)(bB >> 32);
            mma1688(dd[0], ehi[0], ehi[1], hA);
            mma1688(dd[1], ehi[0], ehi[1], hB);
            mma1688(dd[0], elo[0], elo[1], hA);   // lo*hi
            mma1688(dd[1], elo[0], elo[1], hB);
            mma1688(dd[0], ehi[0], ehi[1], lA);   // hi*lo
            mma1688(dd[1], ehi[0], ehi[1], lB);

            u32 Ah[4], Al[4];
            #pragma unroll
            for (int nfo = 0; nfo < 2; nfo++) {
                u32 h01, l01, h23, l23;
                split2(fmaxf(dd[nfo][0], 0.f), fmaxf(dd[nfo][1], 0.f), h01, l01);
                split2(fmaxf(dd[nfo][2], 0.f), fmaxf(dd[nfo][3], 0.f), h23, l23);
                Ah[nfo * 2 + 0] = h01;  Al[nfo * 2 + 0] = l01;
                Ah[nfo * 2 + 1] = h23;  Al[nfo * 2 + 1] = l23;
            }

            // ---- GEMM2 (2-term): 128 cols via 8 nf-pairs ----
            const char* bfp = smem + OFF_BFRAG +
                              (size_t)(kb * 8) * 512 + lane * 16;
            #pragma unroll
            for (int nf2 = 0; nf2 < 8; nf2++) {
                ulonglong2 bf = *(const ulonglong2*)(bfp + nf2 * 512);
                u32 hA0 = (u32)bf.x, hA1 = (u32)(bf.x >> 32);
                u32 hB0 = (u32)bf.y, hB1 = (u32)(bf.y >> 32);
                mma16816(d[2 * nf2],     Ah[0], Ah[1], Ah[2], Ah[3], hA0, hA1);
                mma16816(d[2 * nf2 + 1], Ah[0], Ah[1], Ah[2], Ah[3], hB0, hB1);
                mma16816(d[2 * nf2],     Al[0], Al[1], Al[2], Al[3], hA0, hA1);
                mma16816(d[2 * nf2 + 1], Al[0], Al[1], Al[2], Al[3], hB0, hB1);
            }
        }

        // ---- epilogue: relu(D + b2) . W3 ; per-lane rows via shfl-xor ----
        float s0 = 0.f, s1 = 0.f;
        #pragma unroll
        for (int nf = 0; nf < 16; nf++) {
            float4 bw = *(const float4*)(smem + OFF_BW + (nf * 4 + q) * 16);
            s0 += fmaxf(d[nf][0] + bw.x, 0.f) * bw.z +
                  fmaxf(d[nf][1] + bw.y, 0.f) * bw.w;
            s1 += fmaxf(d[nf][2] + bw.x, 0.f) * bw.z +
                  fmaxf(d[nf][3] + bw.y, 0.f) * bw.w;
        }
        s0 += __shfl_xor_sync(0xFFFFFFFFu, s0, 1);
        s0 += __shfl_xor_sync(0xFFFFFFFFu, s0, 2);
        s1 += __shfl_xor_sync(0xFFFFFFFFu, s1, 1);
        s1 += __shfl_xor_sync(0xFFFFFFFFu, s1, 2);
        act[0] = s0 + b3v;      // act(row gr0), identical in all q lanes
        act[1] = s1 + b3v;      // act(row gr1)
        if (q == 0) {
            out[(size_t)gr0 * kT + t] = act[0];
            out[(size_t)gr1 * kT + t] = act[1];
        }
    }
}

extern "C" void kernel_launch(void* const* d_in, const int* in_sizes, int n_in,
                              void* d_out, int out_size)
{
    (void)in_sizes; (void)n_in; (void)out_size;
    const float* proj  = (const float*)d_in[0];
    const float* idm   = (const float*)d_in[1];
    const float* merg  = (const float*)d_in[2];
    const float* W1    = (const float*)d_in[3];
    const float* b1    = (const float*)d_in[4];
    const float* W2    = (const float*)d_in[5];
    const float* b2    = (const float*)d_in[6];
    const float* W3    = (const float*)d_in[7];
    const float* b3    = (const float*)d_in[8];
    const float* smean = (const float*)d_in[9];
    const float* svar  = (const float*)d_in[10];
    float* out = (float*)d_out;

    cudaFuncSetAttribute(fsim_mma, cudaFuncAttributeMaxDynamicSharedMemorySize,
                         SMEM_BYTES);
    fsim_mma<<<kB / kM, kThreads, SMEM_BYTES>>>(
        proj, idm, merg, W1, b1, W2, b2, W3, b3, smean, svar, out);
}

// round 12
// speedup vs baseline: 1.4670x; 1.0657x over previous
#include <cuda_runtime.h>
#include <cuda_fp16.h>
#include <cstddef>

// ForwardSim, fully tensorized HMMA (sm_103 baseline mma.sync).
// R12 = R11 + exact chip-wide load balance: warps are independent 16-row
// pipelines, so tiles are assigned tileId = w*GRID + blockIdx.x with
// grid = 296 (2 CTAs on every SM, 13-14 ACTIVE warps per SM uniformly,
// instead of R11's 16-vs-8 split across SMs). Inactive warps exit after
// setup. Hot loop unchanged: warp-local, no barriers; GEMM2 2-term fp16
// split (A hi+lo, B hi-only); GEMM1 k8 3-term + exact fp32 feature-8 FMA.

using u32 = unsigned int;
using u64 = unsigned long long;

namespace {
constexpr int kB = 32768, kT = 50, kH = 128, kThreads = 256;
constexpr int GRID = 296;            // 2 x 148 SMs
constexpr int NT   = kB / 16;        // 2048 warp-tiles of 16 rows

constexpr int OFF_BFRAG = 0;        // 32768: W2 hi frags [kb][nf2][lane] 16B
constexpr int OFF_PACC  = 32768;    // 65536: projAcc frags [w][nf1][lane] 16B
constexpr int OFF_W1EB  = 98304;    // 4096:  W1e k8 B-frags [nf1][lane] 8B
constexpr int OFF_W72   = 102400;   // 512:   W1 row 72 natural
constexpr int OFF_BW    = 102912;   // 1024:  (b2 pair, W3 pair) per col pair
constexpr int SMEM_BYTES = 103936;
constexpr int OFF_W1P   = 0;        // phase alias in BFRAG: W1[0:64] natural
} // namespace

__device__ __forceinline__ u64 pack_dup(float v) {
    u64 r; asm("mov.b64 %0, {%1, %1};" : "=l"(r) : "f"(v)); return r;
}
__device__ __forceinline__ u64 pack2(float a, float b) {
    u64 r; asm("mov.b64 %0, {%1, %2};" : "=l"(r) : "f"(a), "f"(b)); return r;
}
__device__ __forceinline__ void unpack2(u64 v, float& a, float& b) {
    asm("mov.b64 {%0, %1}, %2;" : "=f"(a), "=f"(b) : "l"(v));
}
__device__ __forceinline__ u64 fma2(u64 a, u64 b, u64 c) {
    u64 d; asm("fma.rn.f32x2 %0, %1, %2, %3;" : "=l"(d) : "l"(a), "l"(b), "l"(c));
    return d;
}
__device__ __forceinline__ void split2(float f0, float f1, u32& hi, u32& lo) {
    __half h0 = __float2half_rn(f0), h1 = __float2half_rn(f1);
    __half2 hh = __halves2half2(h0, h1);
    hi = reinterpret_cast<u32&>(hh);
    __half2 ll = __floats2half2_rn(f0 - __half2float(h0),
                                   f1 - __half2float(h1));
    lo = reinterpret_cast<u32&>(ll);
}
__device__ __forceinline__ u32 hi2only(float f0, float f1) {
    __half2 hh = __floats2half2_rn(f0, f1);
    return reinterpret_cast<u32&>(hh);
}
__device__ __forceinline__ void mma16816(float d[4], u32 a0, u32 a1, u32 a2,
                                         u32 a3, u32 b0, u32 b1) {
    asm volatile(
        "mma.sync.aligned.m16n8k16.row.col.f32.f16.f16.f32 "
        "{%0,%1,%2,%3}, {%4,%5,%6,%7}, {%8,%9}, {%0,%1,%2,%3};"
        : "+f"(d[0]), "+f"(d[1]), "+f"(d[2]), "+f"(d[3])
        : "r"(a0), "r"(a1), "r"(a2), "r"(a3), "r"(b0), "r"(b1));
}
__device__ __forceinline__ void mma1688(float d[4], u32 a0, u32 a1, u32 b0) {
    asm volatile(
        "mma.sync.aligned.m16n8k8.row.col.f32.f16.f16.f32 "
        "{%0,%1,%2,%3}, {%4,%5}, {%6}, {%0,%1,%2,%3};"
        : "+f"(d[0]), "+f"(d[1]), "+f"(d[2]), "+f"(d[3])
        : "r"(a0), "r"(a1), "r"(b0));
}

__global__ void __launch_bounds__(kThreads, 2)
fsim_mma(const float* __restrict__ proj, const float* __restrict__ idm,
         const float* __restrict__ merg, const float* __restrict__ W1,
         const float* __restrict__ b1,   const float* __restrict__ W2,
         const float* __restrict__ b2,   const float* __restrict__ W3,
         const float* __restrict__ b3,   const float* __restrict__ smean,
         const float* __restrict__ svar, float* __restrict__ out)
{
    extern __shared__ char smem[];
    float* smf = (float*)smem;

    const int tid = threadIdx.x, w = tid >> 5, lane = tid & 31;
    const int g = lane >> 2, q = lane & 3;
    const int bx = blockIdx.x;

    // ---------------- phase A: stage W1[0:64] natural + tables -------------
    for (int i = tid; i < 64 * kH; i += kThreads)
        smf[(OFF_W1P >> 2) + i] = W1[i];
    if (tid < 64) {
        int c = tid * 2;
        float4 v;
        v.x = b2[c]; v.y = b2[c + 1]; v.z = W3[c]; v.w = W3[c + 1];
        *(float4*)(smem + OFF_BW + tid * 16) = v;
    }
    if (tid < 128)
        smf[(OFF_W72 >> 2) + tid] = W1[(size_t)72 * 128 + tid];
    __syncthreads();

    // -------- phase B: projAcc = proj@W1[:64]+b1 -> fragment-native fp32 ---
    // tiles for this CTA: tileId(w) = w*GRID + bx (w = 0..7)
    for (int task = tid; task < 1024; task += kThreads) {
        int t_w = task >> 7, rem = task & 127;
        int lr = rem >> 3, cg = rem & 7;      // row-in-tile, 16-col group
        int tileId = t_w * GRID + bx;
        if (tileId >= NT) continue;
        const float* prow = proj + (size_t)(tileId * 16 + lr) * 64;
        u64 acc[8];
        #pragma unroll
        for (int e = 0; e < 8; e++)
            acc[e] = pack2(__ldg(&b1[cg * 16 + 2 * e]),
                           __ldg(&b1[cg * 16 + 2 * e + 1]));
        #pragma unroll 4
        for (int k4 = 0; k4 < 16; k4++) {
            float4 av = __ldg((const float4*)(prow + k4 * 4));
            float avv[4] = {av.x, av.y, av.z, av.w};
            #pragma unroll
            for (int e2 = 0; e2 < 4; e2++) {
                u64 a = pack_dup(avv[e2]);
                const u64* ww = (const u64*)
                    &smf[(OFF_W1P >> 2) + (k4 * 4 + e2) * 128 + cg * 16];
                #pragma unroll
                for (int e = 0; e < 8; e++) acc[e] = fma2(a, ww[e], acc[e]);
            }
        }
        int half = (lr >> 3) & 1, lrow = lr & 7;
        #pragma unroll
        for (int e = 0; e < 8; e++) {
            int nf1 = cg * 2 + (e >> 2);
            int ln  = lrow * 4 + (e & 3);
            float lo_, hi_;
            unpack2(acc[e], lo_, hi_);
            *(float2*)(smem + OFF_PACC +
                       (size_t)(((t_w * 16 + nf1) * 32 + ln) * 16) + half * 8)
                = make_float2(lo_, hi_);
        }
    }
    __syncthreads();

    // ---- phase C: W2 -> hi-only frags packed per nf-pair (overwrites W1P) -
    for (int i = tid; i < 2048; i += kThreads) {
        int t  = i & 31, nf2 = (i >> 5) & 7, kb = (i >> 8) & 7;
        int gg = t >> 2, qq = t & 3;
        int k0 = kb * 16 + qq * 2;
        int nA = nf2 * 16 + gg;
        int nB = nA + 8;
        u32 hA0 = hi2only(W2[(size_t)k0 * 128 + nA],
                          W2[(size_t)(k0 + 1) * 128 + nA]);
        u32 hA1 = hi2only(W2[(size_t)(k0 + 8) * 128 + nA],
                          W2[(size_t)(k0 + 9) * 128 + nA]);
        u32 hB0 = hi2only(W2[(size_t)k0 * 128 + nB],
                          W2[(size_t)(k0 + 1) * 128 + nB]);
        u32 hB1 = hi2only(W2[(size_t)(k0 + 8) * 128 + nB],
                          W2[(size_t)(k0 + 9) * 128 + nB]);
        ulonglong2 e;
        e.x = ((u64)hA1 << 32) | hA0;
        e.y = ((u64)hB1 << 32) | hB0;
        *(ulonglong2*)(smem + OFF_BFRAG +
                       (size_t)((kb * 8 + nf2) * 32 + t) * 16) = e;
    }
    // -------- phase C2: W1e rows 64..71 -> k8 B-frags [hi u32 | lo u32] ----
    for (int i = tid; i < 512; i += kThreads) {
        int t = i & 31, nf = i >> 5;        // nf1 0..15
        int gg = t >> 2, qq = t & 3;
        int n  = nf * 8 + gg;
        int k0 = qq * 2;
        float w00 = W1[(size_t)(64 + k0) * 128 + n];
        float w01 = W1[(size_t)(64 + k0 + 1) * 128 + n];
        u32 h, l;
        split2(w00, w01, h, l);
        *(u64*)(smem + OFF_W1EB + (size_t)(nf * 32 + t) * 8) =
            ((u64)l << 32) | h;
    }
    __syncthreads();

    // ---------------- warp tile; inactive warps exit ----------------
    const int tileId = w * GRID + bx;
    if (tileId >= NT) return;

    const float b3v = __ldg(&b3[0]);
    const int gr0 = tileId * 16 + g;           // this lane's two rows
    const int gr1 = gr0 + 8;
    // scaler consts for features j = 2q, 2q+1 (q==3 -> mc passthrough)
    float scm0 = 0.f, scm1 = 0.f, sci0 = 1.f, sci1 = 1.f;
    if (q < 3) {
        scm0 = __ldg(&smean[2 * q]);
        scm1 = __ldg(&smean[2 * q + 1]);
        sci0 = rsqrtf(__ldg(&svar[2 * q]));
        sci1 = rsqrtf(__ldg(&svar[2 * q + 1]));
    }

    // carry + prefetch (per lane, both rows; redundant over q — no comms)
    float egv[2], egx[2], act[2] = {0.f, 0.f};
    float4 pa[2];
    float ps4[2], ps5[2], ps11[2], pm0[2], pm1[2], pm2[2];
    #pragma unroll
    for (int i = 0; i < 2; i++) {
        int gr = (i == 0) ? gr0 : gr1;
        const float* sp = idm + (size_t)gr * (kT * 12);
        pa[i] = __ldg((const float4*)sp);
        float2 s45 = __ldg((const float2*)(sp + 4));
        ps4[i] = s45.x; ps5[i] = s45.y;
        ps11[i] = __ldg(sp + 11);
        const float* mp = merg + (size_t)gr * (kT * 3);
        pm0[i] = __ldg(mp); pm1[i] = __ldg(mp + 1); pm2[i] = __ldg(mp + 2);
    }

    // ================= timestep loop (warp-local, no barriers) =============
    for (int t = 0; t < kT; t++) {
        // ---- env features + A-fragments, in registers ----
        u32 ehi[2], elo[2];
        float e8v[2];
        #pragma unroll
        for (int i = 0; i < 2; i++) {
            if (t == 0) { egv[i] = pa[i].x; egx[i] = pa[i].w; }
            else {
                egv[i] = fmaf(act[i], 0.1f, egv[i]);
                egx[i] = egx[i] + egv[i] * 0.1f + act[i] * 0.005f;
            }
            float f0 = egv[i];
            float f1 = pa[i].y;
            float f2 = egv[i] - pa[i].y;
            float f3 = ps4[i] - egx[i];
            float f4 = (egv[i] - pa[i].z) * ps11[i];
            float f5 = (ps5[i] - egx[i]) * ps11[i] + (1.0f - ps11[i]) * 100.0f;
            float fa, fb;
            if      (q == 0) { fa = f0; fb = f1; }
            else if (q == 1) { fa = f2; fb = f3; }
            else if (q == 2) { fa = f4; fb = f5; }
            else             { fa = pm0[i]; fb = pm1[i]; }
            fa = (fa - scm0) * sci0;
            fb = (fb - scm1) * sci1;
            split2(fa, fb, ehi[i], elo[i]);
            e8v[i] = pm2[i];
        }

        // ---- prefetch t+1 (hidden under the mma phase) ----
        if (t + 1 < kT) {
            #pragma unroll
            for (int i = 0; i < 2; i++) {
                int gr = (i == 0) ? gr0 : gr1;
                const float* sp = idm + (size_t)gr * (kT * 12) + (t + 1) * 12;
                pa[i] = __ldg((const float4*)sp);
                float2 s45 = __ldg((const float2*)(sp + 4));
                ps4[i] = s45.x; ps5[i] = s45.y;
                ps11[i] = __ldg(sp + 11);
                const float* mp = merg + (size_t)gr * (kT * 3) + (t + 1) * 3;
                pm0[i] = __ldg(mp); pm1[i] = __ldg(mp + 1); pm2[i] = __ldg(mp + 2);
            }
        }

        float d[16][4];
        #pragma unroll
        for (int nf = 0; nf < 16; nf++)
            d[nf][0] = d[nf][1] = d[nf][2] = d[nf][3] = 0.f;

        for (int kb = 0; kb < 8; kb++) {
            // ---- GEMM1 (k8, 3-term) + exact feature-8 FMA ----
            int nf1 = kb * 2;
            float4 pv0 = *(const float4*)(smem + OFF_PACC +
                (size_t)(((w * 16 + nf1) * 32 + lane) * 16));
            float4 pv1 = *(const float4*)(smem + OFF_PACC +
                (size_t)(((w * 16 + nf1 + 1) * 32 + lane) * 16));
            u64 bA = *(const u64*)(smem + OFF_W1EB +
                (size_t)((nf1 * 32 + lane) * 8));
            u64 bB = *(const u64*)(smem + OFF_W1EB +
                (size_t)(((nf1 + 1) * 32 + lane) * 8));
            float2 wA = *(const float2*)(smem + OFF_W72 + (nf1 * 4 + q) * 8);
            float2 wB = *(const float2*)(smem + OFF_W72 + ((nf1 + 1) * 4 + q) * 8);
            float dd[2][4];
            dd[0][0] = fmaf(e8v[0], wA.x, pv0.x);
            dd[0][1] = fmaf(e8v[0], wA.y, pv0.y);
            dd[0][2] = fmaf(e8v[1], wA.x, pv0.z);
            dd[0][3] = fmaf(e8v[1], wA.y, pv0.w);
            dd[1][0] = fmaf(e8v[0], wB.x, pv1.x);
            dd[1][1] = fmaf(e8v[0], wB.y, pv1.y);
            dd[1][2] = fmaf(e8v[1], wB.x, pv1.z);
            dd[1][3] = fmaf(e8v[1], wB.y, pv1.w);
            u32 hA = (u32)bA, lA = (u32)(bA >> 32);
            u32 hB = (u32)bB, lB = (u32)(bB >> 32);
            mma1688(dd[0], ehi[0], ehi[1], hA);
            mma1688(dd[1], ehi[0], ehi[1], hB);
            mma1688(dd[0], elo[0], elo[1], hA);   // lo*hi
            mma1688(dd[1], elo[0], elo[1], hB);
            mma1688(dd[0], ehi[0], ehi[1], lA);   // hi*lo
            mma1688(dd[1], ehi[0], ehi[1], lB);

            u32 Ah[4], Al[4];
            #pragma unroll
            for (int nfo = 0; nfo < 2; nfo++) {
                u32 h01, l01, h23, l23;
                split2(fmaxf(dd[nfo][0], 0.f), fmaxf(dd[nfo][1], 0.f), h01, l01);
                split2(fmaxf(dd[nfo][2], 0.f), fmaxf(dd[nfo][3], 0.f), h23, l23);
                Ah[nfo * 2 + 0] = h01;  Al[nfo * 2 + 0] = l01;
                Ah[nfo * 2 + 1] = h23;  Al[nfo * 2 + 1] = l23;
            }

            // ---- GEMM2 (2-term): 128 cols via 8 nf-pairs ----
            const char* bfp = smem + OFF_BFRAG +
                              (size_t)(kb * 8) * 512 + lane * 16;
            #pragma unroll
            for (int nf2 = 0; nf2 < 8; nf2++) {
                ulonglong2 bf = *(const ulonglong2*)(bfp + nf2 * 512);
                u32 hA0 = (u32)bf.x, hA1 = (u32)(bf.x >> 32);
                u32 hB0 = (u32)bf.y, hB1 = (u32)(bf.y >> 32);
                mma16816(d[2 * nf2],     Ah[0], Ah[1], Ah[2], Ah[3], hA0, hA1);
                mma16816(d[2 * nf2 + 1], Ah[0], Ah[1], Ah[2], Ah[3], hB0, hB1);
                mma16816(d[2 * nf2],     Al[0], Al[1], Al[2], Al[3], hA0, hA1);
                mma16816(d[2 * nf2 + 1], Al[0], Al[1], Al[2], Al[3], hB0, hB1);
            }
        }

        // ---- epilogue: relu(D + b2) . W3 ; per-lane rows via shfl-xor ----
        float s0 = 0.f, s1 = 0.f;
        #pragma unroll
        for (int nf = 0; nf < 16; nf++) {
            float4 bw = *(const float4*)(smem + OFF_BW + (nf * 4 + q) * 16);
            s0 += fmaxf(d[nf][0] + bw.x, 0.f) * bw.z +
                  fmaxf(d[nf][1] + bw.y, 0.f) * bw.w;
            s1 += fmaxf(d[nf][2] + bw.x, 0.f) * bw.z +
                  fmaxf(d[nf][3] + bw.y, 0.f) * bw.w;
        }
        s0 += __shfl_xor_sync(0xFFFFFFFFu, s0, 1);
        s0 += __shfl_xor_sync(0xFFFFFFFFu, s0, 2);
        s1 += __shfl_xor_sync(0xFFFFFFFFu, s1, 1);
        s1 += __shfl_xor_sync(0xFFFFFFFFu, s1, 2);
        act[0] = s0 + b3v;      // act(row gr0), identical in all q lanes
        act[1] = s1 + b3v;      // act(row gr1)
        if (q == 0) {
            out[(size_t)gr0 * kT + t] = act[0];
            out[(size_t)gr1 * kT + t] = act[1];
        }
    }
}

extern "C" void kernel_launch(void* const* d_in, const int* in_sizes, int n_in,
                              void* d_out, int out_size)
{
    (void)in_sizes; (void)n_in; (void)out_size;
    const float* proj  = (const float*)d_in[0];
    const float* idm   = (const float*)d_in[1];
    const float* merg  = (const float*)d_in[2];
    const float* W1    = (const float*)d_in[3];
    const float* b1    = (const float*)d_in[4];
    const float* W2    = (const float*)d_in[5];
    const float* b2    = (const float*)d_in[6];
    const float* W3    = (const float*)d_in[7];
    const float* b3    = (const float*)d_in[8];
    const float* smean = (const float*)d_in[9];
    const float* svar  = (const float*)d_in[10];
    float* out = (float*)d_out;

    cudaFuncSetAttribute(fsim_mma, cudaFuncAttributeMaxDynamicSharedMemorySize,
                         SMEM_BYTES);
    fsim_mma<<<GRID, kThreads, SMEM_BYTES>>>(
        proj, idm, merg, W1, b1, W2, b2, W3, b3, smean, svar, out);
}